// round 1
// baseline (speedup 1.0000x reference)
#include <cuda_runtime.h>

// Lorentz boost applied per-channel:
//   out[b,c,i] = B(Bo[c])[i,j] * T[b,c,j]
// where B = I - g*mag*nK + (g-1)*nK^2, which reduces analytically to:
//   y0 = g*(x0 - mag*(n.x))
//   yi = xi + n_i * ((g-1)*(n.x) - g*mag*x0)
//
// T: (8192, 1024, 4) fp32, Bo: (1024, 3) fp32.
// Pure HBM-streaming kernel: 256 MiB total traffic; coefficients computed
// once per thread (one channel) and held in registers across the b-loop.

#define NB 8192
#define NC 1024
#define ROWS_PER_BLOCK 32
#define THREADS 256
#define EPS 1e-7f

__global__ __launch_bounds__(THREADS)
void lorentz_boost_kernel(const float* __restrict__ T,
                          const float* __restrict__ Bo,
                          float* __restrict__ out)
{
    const int c = blockIdx.x * THREADS + threadIdx.x;   // channel, 0..1023
    const int b0 = blockIdx.y * ROWS_PER_BLOCK;         // batch slab start

    // Per-channel boost coefficients (amortized over ROWS_PER_BLOCK rows).
    const float bx = Bo[c * 3 + 0];
    const float by = Bo[c * 3 + 1];
    const float bz = Bo[c * 3 + 2];
    float mag = sqrtf(bx * bx + by * by + bz * bz);
    mag = fminf(fmaxf(mag, EPS), 1.0f - EPS);
    const float inv_mag = 1.0f / mag;
    const float n1 = bx * inv_mag;
    const float n2 = by * inv_mag;
    const float n3 = bz * inv_mag;
    const float g  = rsqrtf(fmaxf(1.0f - mag * mag, 1e-30f));
    const float gm = g * mag;        // g*mag
    const float gm1 = g - 1.0f;      // (g-1)

    // Stream down the batch dimension: float4 per (b,c).
    const float4* __restrict__ Tin  = (const float4*)T;
    float4* __restrict__ Oout = (float4*)out;

    const long base = (long)b0 * NC + c;

    #pragma unroll 8
    for (int r = 0; r < ROWS_PER_BLOCK; ++r) {
        const long idx = base + (long)r * NC;
        float4 v = Tin[idx];

        const float s = n1 * v.y + n2 * v.z + n3 * v.w;   // n . x
        float4 y;
        y.x = g * (v.x - mag * s);
        const float w = gm1 * s - gm * v.x;
        y.y = v.y + n1 * w;
        y.z = v.z + n2 * w;
        y.w = v.w + n3 * w;

        Oout[idx] = y;
    }
}

extern "C" void kernel_launch(void* const* d_in, const int* in_sizes, int n_in,
                              void* d_out, int out_size)
{
    const float* T  = (const float*)d_in[0];   // (8192, 1024, 4)
    const float* Bo = (const float*)d_in[1];   // (1024, 3)
    float* out = (float*)d_out;

    dim3 grid(NC / THREADS, NB / ROWS_PER_BLOCK);  // (4, 256)
    lorentz_boost_kernel<<<grid, THREADS>>>(T, Bo, out);
}

// round 4
// speedup vs baseline: 1.1031x; 1.1031x over previous
#include <cuda_runtime.h>

// Lorentz boost applied per-channel:
//   out[b,c,i] = B(Bo[c])[i,j] * T[b,c,j]
// with B = I - g*mag*nK + (g-1)*nK^2 reduced analytically to:
//   y0 = g*(x0 - mag*(n.x))
//   yi = xi + n_i * ((g-1)*(n.x) - g*mag*x0)
//
// T: (8192, 1024, 4) fp32.  Pure HBM streaming, 256 MiB total traffic.
// R1 lesson: 1024 fat CTAs ran as one uneven wave -> DRAM stuck at 68.9%.
// R2/R3 (unmeasured, broker timeouts): 4096 short CTAs (8 rows each),
// front-batched loads (MLP=8), streaming cache hints. Target ~80% DRAM.

#define NB 8192
#define NC 1024
#define ROWS_PER_BLOCK 8
#define THREADS 256
#define EPS 1e-7f

__global__ __launch_bounds__(THREADS)
void lorentz_boost_kernel(const float4* __restrict__ T,
                          const float* __restrict__ Bo,
                          float4* __restrict__ out)
{
    const int c  = blockIdx.x * THREADS + threadIdx.x;   // channel 0..1023
    const int b0 = blockIdx.y * ROWS_PER_BLOCK;          // batch slab start

    // Per-channel boost coefficients (registers for the whole slab).
    const float bx = Bo[c * 3 + 0];
    const float by = Bo[c * 3 + 1];
    const float bz = Bo[c * 3 + 2];
    float mag = sqrtf(bx * bx + by * by + bz * bz);
    mag = fminf(fmaxf(mag, EPS), 1.0f - EPS);
    const float inv_mag = 1.0f / mag;
    const float n1 = bx * inv_mag;
    const float n2 = by * inv_mag;
    const float n3 = bz * inv_mag;
    const float g   = rsqrtf(fmaxf(1.0f - mag * mag, 1e-30f));
    const float gm  = g * mag;
    const float gm1 = g - 1.0f;

    const int base = b0 * NC + c;   // max 8M, fits int32

    // Front-batch all 8 loads: guarantees MLP=8 per thread.
    float4 v[ROWS_PER_BLOCK];
    #pragma unroll
    for (int r = 0; r < ROWS_PER_BLOCK; ++r)
        v[r] = __ldcs(&T[base + r * NC]);

    #pragma unroll
    for (int r = 0; r < ROWS_PER_BLOCK; ++r) {
        const float s = n1 * v[r].y + n2 * v[r].z + n3 * v[r].w;  // n . x
        float4 y;
        y.x = g * (v[r].x - mag * s);
        const float w = gm1 * s - gm * v[r].x;
        y.y = v[r].y + n1 * w;
        y.z = v[r].z + n2 * w;
        y.w = v[r].w + n3 * w;
        __stcs(&out[base + r * NC], y);
    }
}

extern "C" void kernel_launch(void* const* d_in, const int* in_sizes, int n_in,
                              void* d_out, int out_size)
{
    const float4* T  = (const float4*)d_in[0];   // (8192, 1024, 4)
    const float* Bo  = (const float*)d_in[1];    // (1024, 3)
    float4* out = (float4*)d_out;

    dim3 grid(NC / THREADS, NB / ROWS_PER_BLOCK);  // (4, 1024) = 4096 CTAs
    lorentz_boost_kernel<<<grid, THREADS>>>(T, Bo, out);
}